// round 8
// baseline (speedup 1.0000x reference)
#include <cuda_runtime.h>

// ---------------------------------------------------------------------------
// DeepGCN fused kernel, round 7.
//  - Graphs independent -> entire 20-layer res+ scan fused, h in registers.
//  - Scatter-add replaced by per-graph 23x23 edge-multiplicity matrix A
//    (agg = A @ z), built once per launch.
//  - Packed fp32 math via PTX fma.rn.f32x2 (double-rate on sm_103a).
//  - One THREAD per node. R6 regression root-caused to register spills
//    (256thr/2blk -> 128-reg cap vs 88 regs of persistent state). Fix:
//    192-thread blocks (8 graphs, 184 nodes) -> 170-reg cap, no spills,
//    2 blocks/SM -> 12 warps/SM.
// ---------------------------------------------------------------------------

static constexpr int NUM_GRAPHS = 16384;
static constexpr int NG        = 23;       // nodes per graph
static constexpr int E_TOTAL   = 4194304;  // total edges
static constexpr int HDIM      = 64;
static constexpr int NLAYERS   = 20;
static constexpr int NB        = 1024;     // clips
static constexpr int NT        = 16;       // window
static constexpr int NC        = 3;        // classes
static constexpr int A_STRIDE  = NG * NG;  // 529

static constexpr int TPB      = 192;       // threads per block (6 warps)
static constexpr int GPB      = 8;         // graphs per block (8*23 = 184)
static constexpr int NODES_PB = GPB * NG;  // 184
static constexpr int ZSTRIDE  = 24;        // z column stride (23 + zero pad)
static constexpr int ZBUF     = HDIM * ZSTRIDE;  // 1536 floats per graph

// Shared layout (floats):
//  [0, 4096)      W_rel  (current layer)
//  [4096, 8192)   W_root (current layer)
//  [8192, 8256)   ln_g
//  [8256, 8320)   ln_b
//  [8320, 8384)   b_rel
//  [8384, 8896)   W_enc
//  [8896, 8960)   b_enc
//  [8960, +GPB*1536) per-graph z buffers (transposed: z[f*24 + node])
static constexpr int SM_FLOATS = 8960 + GPB * ZBUF;  // 21248
static constexpr int SM_BYTES  = SM_FLOATS * 4;      // 84992 B -> 2 blocks/SM

// Device scratch (allocation-free rule: __device__ globals)
__device__ float g_A[(size_t)NUM_GRAPHS * A_STRIDE];   // ~34.7 MB
__device__ float g_pooled[(size_t)NUM_GRAPHS * HDIM];  // 4 MB

// ---------------------------------------------------------------------------
// f32x2 packed helpers (only reachable via PTX on sm_103a)
// ---------------------------------------------------------------------------
typedef unsigned long long u64t;

__device__ __forceinline__ u64t pk2(float lo, float hi) {
    u64t r;
    asm("mov.b64 %0, {%1, %2};" : "=l"(r) : "f"(lo), "f"(hi));
    return r;
}
__device__ __forceinline__ void upk2(u64t v, float& lo, float& hi) {
    asm("mov.b64 {%0, %1}, %2;" : "=f"(lo), "=f"(hi) : "l"(v));
}
__device__ __forceinline__ u64t fma2(u64t a, u64t b, u64t c) {
    u64t d;
    asm("fma.rn.f32x2 %0, %1, %2, %3;" : "=l"(d) : "l"(a), "l"(b), "l"(c));
    return d;
}
__device__ __forceinline__ u64t add2(u64t a, u64t b) {
    u64t d;
    asm("add.rn.f32x2 %0, %1, %2;" : "=l"(d) : "l"(a), "l"(b));
    return d;
}
__device__ __forceinline__ u64t mul2(u64t a, u64t b) {
    u64t d;
    asm("mul.rn.f32x2 %0, %1, %2;" : "=l"(d) : "l"(a), "l"(b));
    return d;
}

// ---------------------------------------------------------------------------
__global__ void zeroA_kernel() {
    const int n4 = NUM_GRAPHS * A_STRIDE / 4;
    float4* p = reinterpret_cast<float4*>(g_A);
    for (int i = blockIdx.x * blockDim.x + threadIdx.x; i < n4;
         i += gridDim.x * blockDim.x)
        p[i] = make_float4(0.f, 0.f, 0.f, 0.f);
}

__global__ void buildA_kernel(const int* __restrict__ ei) {
    int e = blockIdx.x * blockDim.x + threadIdx.x;
    if (e >= E_TOTAL) return;
    int s = ei[e];            // global src id
    int d = ei[E_TOTAL + e];  // global dst id
    int g  = d / NG;
    int li = d - g * NG;      // local dst
    int lj = s - g * NG;      // local src (same graph by construction)
    atomicAdd(&g_A[(size_t)g * A_STRIDE + li * NG + lj], 1.0f);
}

// ---------------------------------------------------------------------------
// Main fused kernel: encoder + 20 layers + per-graph mean pool.
// One thread per node; block = 8 graphs. h packed f32x2 in registers.
// ---------------------------------------------------------------------------
__global__ void __launch_bounds__(TPB, 2) gcn_main(
    const float* __restrict__ x,
    const float* __restrict__ W_enc, const float* __restrict__ b_enc,
    const float* __restrict__ ln_g,  const float* __restrict__ ln_b,
    const float* __restrict__ W_rel, const float* __restrict__ b_rel,
    const float* __restrict__ W_root)
{
    extern __shared__ float sm[];
    float* wrel_s  = sm;
    float* wroot_s = sm + 4096;
    float* lng_s   = sm + 8192;
    float* lnb_s   = sm + 8256;
    float* brel_s  = sm + 8320;
    float* wenc_s  = sm + 8384;
    float* benc_s  = sm + 8896;
    float* zall    = sm + 8960;

    const int t = threadIdx.x;
    int gl   = t / NG;              // local graph 0..7 (for t<184)
    int node = t - gl * NG;         // local node 0..22
    if (gl >= GPB) { gl = GPB - 1; node = 0; }   // keep pointers in-range
    const int g    = blockIdx.x * GPB + gl;
    const bool act = (t < NODES_PB);
    float* zs = zall + gl * ZBUF;

    // one-time: encoder weights to shared; zero all z buffers (pads stay 0)
    for (int i = t; i < 512; i += TPB) wenc_s[i] = W_enc[i];
    if (t < HDIM) benc_s[t] = b_enc[t];
    for (int i = t; i < GPB * ZBUF; i += TPB) zall[i] = 0.f;
    __syncthreads();

    u64t h2[HDIM / 2];   // packed h (f32x2): 64 regs
    u64t Ap[12];         // packed A row (23 + zero pad): 24 regs

    if (act) {
        // encoder: h = x @ W_enc + b_enc   (x row: 8 floats, 32B aligned)
        const float4* xr = reinterpret_cast<const float4*>(
            x + (size_t)(g * NG + node) * 8);
        float4 xa = xr[0], xb = xr[1];
        float xv[8] = {xa.x, xa.y, xa.z, xa.w, xb.x, xb.y, xb.z, xb.w};
        #pragma unroll
        for (int p = 0; p < HDIM / 2; p++) {
            float v0 = benc_s[2 * p], v1 = benc_s[2 * p + 1];
            #pragma unroll
            for (int k = 0; k < 8; k++) {
                v0 = fmaf(xv[k], wenc_s[k * HDIM + 2 * p],     v0);
                v1 = fmaf(xv[k], wenc_s[k * HDIM + 2 * p + 1], v1);
            }
            h2[p] = pk2(v0, v1);
        }
        // packed A row (constant across layers)
        const float* Ar = g_A + (size_t)g * A_STRIDE + node * NG;
        #pragma unroll
        for (int j = 0; j < 11; j++) Ap[j] = pk2(Ar[2 * j], Ar[2 * j + 1]);
        Ap[11] = pk2(Ar[22], 0.f);   // pad pairs with zeroed z pad entry
    } else {
        #pragma unroll
        for (int p = 0; p < HDIM / 2; p++) h2[p] = 0ull;
        #pragma unroll
        for (int j = 0; j < 12; j++) Ap[j] = 0ull;
    }

    const u64t neg1 = pk2(-1.f, -1.f);

    for (int l = 0; l < NLAYERS; l++) {
        __syncthreads();  // prev layer's weight + z reads complete
        // stage this layer's weights
        {
            const float4* Wr4 = reinterpret_cast<const float4*>(W_rel)  + l * 1024;
            const float4* Wo4 = reinterpret_cast<const float4*>(W_root) + l * 1024;
            float4* dr = reinterpret_cast<float4*>(wrel_s);
            float4* dq = reinterpret_cast<float4*>(wroot_s);
            for (int i = t; i < 1024; i += TPB) { dr[i] = Wr4[i]; dq[i] = Wo4[i]; }
            if (t < HDIM) {
                lng_s[t]  = ln_g[l * HDIM + t];
                lnb_s[t]  = ln_b[l * HDIM + t];
                brel_s[t] = b_rel[l * HDIM + t];
            }
        }
        __syncthreads();

        // z = relu(LayerNorm(h)) -> shared (transposed: z[f*24 + node])
        if (act) {
            const u64t* g8 = reinterpret_cast<const u64t*>(lng_s);
            const u64t* q8 = reinterpret_cast<const u64t*>(lnb_s);
            // mean
            u64t s2 = h2[0];
            #pragma unroll
            for (int p = 1; p < 32; p++) s2 = add2(s2, h2[p]);
            float slo, shi; upk2(s2, slo, shi);
            float mu = (slo + shi) * (1.f / HDIM);
            u64t mu2 = pk2(mu, mu);
            // var
            u64t v2 = 0ull;
            #pragma unroll
            for (int p = 0; p < 32; p++) {
                u64t d = fma2(mu2, neg1, h2[p]);
                v2 = fma2(d, d, v2);
            }
            float vlo, vhi; upk2(v2, vlo, vhi);
            float rs = rsqrtf((vlo + vhi) * (1.f / HDIM) + 1e-5f);
            u64t rs2 = pk2(rs, rs);
            // z -> shared
            #pragma unroll
            for (int p = 0; p < 32; p++) {
                u64t d  = fma2(mu2, neg1, h2[p]);
                u64t m  = mul2(d, rs2);
                u64t zz = fma2(m, g8[p], q8[p]);
                float zlo, zhi; upk2(zz, zlo, zhi);
                zs[(2 * p)     * ZSTRIDE + node] = fmaxf(zlo, 0.f);
                zs[(2 * p + 1) * ZSTRIDE + node] = fmaxf(zhi, 0.f);
            }
        }
        __syncthreads();   // z visible to all nodes of the graph

        // h += b_rel + (A@z) @ W_rel + z @ W_root     (packed f32x2)
        if (act) {
            const u64t* br8 = reinterpret_cast<const u64t*>(brel_s);
            #pragma unroll
            for (int p = 0; p < 32; p++) h2[p] = add2(h2[p], br8[p]);

            #pragma unroll 2
            for (int k = 0; k < HDIM; k++) {
                const float* zc = zs + k * ZSTRIDE;       // column k (24 floats)
                const ulonglong2* z2 = reinterpret_cast<const ulonglong2*>(zc);

                // agg[node][k] = Arow . z(:,k) — two chains of 6 FMA2
                u64t acc0 = 0ull, acc1 = 0ull;
                #pragma unroll
                for (int j = 0; j < 3; j++) {
                    ulonglong2 za = z2[2 * j];
                    ulonglong2 zb = z2[2 * j + 1];
                    acc0 = fma2(Ap[4 * j],     za.x, acc0);
                    acc1 = fma2(Ap[4 * j + 1], za.y, acc1);
                    acc0 = fma2(Ap[4 * j + 2], zb.x, acc0);
                    acc1 = fma2(Ap[4 * j + 3], zb.y, acc1);
                }
                u64t accs = add2(acc0, acc1);
                float alo, ahi; upk2(accs, alo, ahi);
                float av = alo + ahi;
                u64t a2  = pk2(av, av);
                float zk = zc[node];
                u64t zk2 = pk2(zk, zk);

                const ulonglong2* wr2 =
                    reinterpret_cast<const ulonglong2*>(wrel_s + k * HDIM);
                const ulonglong2* wo2 =
                    reinterpret_cast<const ulonglong2*>(wroot_s + k * HDIM);
                #pragma unroll
                for (int q = 0; q < 16; q++) {
                    ulonglong2 w1 = wr2[q];
                    ulonglong2 w2 = wo2[q];
                    h2[2 * q]     = fma2(a2, w1.x, fma2(zk2, w2.x, h2[2 * q]));
                    h2[2 * q + 1] = fma2(a2, w1.y, fma2(zk2, w2.y, h2[2 * q + 1]));
                }
            }
        }
    }

    // per-graph mean pool (reuse z buffers to stage h)
    __syncthreads();
    if (act) {
        #pragma unroll
        for (int p = 0; p < 32; p++) {
            float lo, hi;
            upk2(h2[p], lo, hi);
            zs[(2 * p)     * ZSTRIDE + node] = lo;
            zs[(2 * p + 1) * ZSTRIDE + node] = hi;
        }
    }
    __syncthreads();
    for (int idx = t; idx < GPB * HDIM; idx += TPB) {
        int gg = idx / HDIM;              // local graph
        int f  = idx - gg * HDIM;
        int gout = blockIdx.x * GPB + gg;
        const float* zb = zall + gg * ZBUF + f * ZSTRIDE;
        float s = 0.f;
        #pragma unroll
        for (int i = 0; i < NG; i++) s += zb[i];
        g_pooled[(size_t)gout * HDIM + f] = s * (1.f / NG);
    }
}

// ---------------------------------------------------------------------------
// Head: xt = pooled.reshape(B,T,H)+pos; v = mean_t; out = relu(v@W1+b1)@W2+b2
// ---------------------------------------------------------------------------
__global__ void head_kernel(const float* __restrict__ pos,
                            const float* __restrict__ W1, const float* __restrict__ b1,
                            const float* __restrict__ W2, const float* __restrict__ b2,
                            float* __restrict__ out)
{
    __shared__ float vs[HDIM];
    __shared__ float h1s[HDIM];
    const int b = blockIdx.x;
    const int f = threadIdx.x;

    float v = 0.f;
    #pragma unroll
    for (int tt = 0; tt < NT; tt++)
        v += g_pooled[(size_t)(b * NT + tt) * HDIM + f] + pos[tt * HDIM + f];
    vs[f] = v * (1.f / NT);
    __syncthreads();

    float acc = b1[f];
    #pragma unroll
    for (int k = 0; k < HDIM; k++) acc = fmaf(vs[k], W1[k * HDIM + f], acc);
    h1s[f] = fmaxf(acc, 0.f);
    __syncthreads();

    if (f < NC) {
        float o = b2[f];
        #pragma unroll
        for (int k = 0; k < HDIM; k++) o = fmaf(h1s[k], W2[k * NC + f], o);
        out[b * NC + f] = o;
    }
}

// ---------------------------------------------------------------------------
extern "C" void kernel_launch(void* const* d_in, const int* in_sizes, int n_in,
                              void* d_out, int out_size)
{
    const float* x     = (const float*)d_in[0];
    const int*   ei    = (const int*)  d_in[1];
    // d_in[2] = batch (unused: graphs are contiguous blocks of 23 nodes)
    const float* W_enc = (const float*)d_in[3];
    const float* b_enc = (const float*)d_in[4];
    const float* ln_g  = (const float*)d_in[5];
    const float* ln_b  = (const float*)d_in[6];
    const float* W_rel = (const float*)d_in[7];
    const float* b_rel = (const float*)d_in[8];
    const float* W_root= (const float*)d_in[9];
    const float* pos   = (const float*)d_in[10];
    const float* W1    = (const float*)d_in[11];
    const float* b1    = (const float*)d_in[12];
    const float* W2    = (const float*)d_in[13];
    const float* b2    = (const float*)d_in[14];
    float* out = (float*)d_out;

    (void)in_sizes; (void)n_in; (void)out_size;

    cudaFuncSetAttribute(gcn_main, cudaFuncAttributeMaxDynamicSharedMemorySize,
                         SM_BYTES);

    zeroA_kernel<<<1024, 256>>>();
    buildA_kernel<<<(E_TOTAL + 255) / 256, 256>>>(ei);
    const int grid = NUM_GRAPHS / GPB;   // 2048
    gcn_main<<<grid, TPB, SM_BYTES>>>(
        x, W_enc, b_enc, ln_g, ln_b, W_rel, b_rel, W_root);
    head_kernel<<<NB, HDIM>>>(pos, W1, b1, W2, b2, out);
}

// round 11
// speedup vs baseline: 1.4355x; 1.4355x over previous
#include <cuda_runtime.h>
#include <cstdint>

// ---------------------------------------------------------------------------
// DeepGCN fused kernel, round 10: tensor cores, reformulated layer algebra.
//
//   Z = relu(LN(H));  P = Z @ [Wr | Wo]  (3xTF32 split products);
//   H += A @ P[:, :64] + P[:, 64:] + b_rel   (A exact in tf32, Q split 2x).
//
// Associativity removes the U=A@Z intermediate split entirely (prime suspect
// for R9's precision leak). Block = 4 graphs (96 rows incl pad rows),
// 8 warps, ~184KB smem, 1 block/SM.
// ---------------------------------------------------------------------------

static constexpr int NUM_GRAPHS = 16384;
static constexpr int NG        = 23;
static constexpr int E_TOTAL   = 4194304;
static constexpr int HDIM      = 64;
static constexpr int NLAYERS   = 20;
static constexpr int NB        = 1024;
static constexpr int NT        = 16;
static constexpr int NC        = 3;
static constexpr int A_STRIDE  = NG * NG;    // 529

static constexpr int G    = 4;               // graphs per block
static constexpr int TPB  = 256;             // 8 warps
static constexpr int MROW = G * 24;          // 96 rows
static constexpr int LDH  = 68;              // H/Z stride  (conflict-free A-frag)
static constexpr int LDP  = 72;              // P stride    (conflict-free B-frag)
static constexpr int LDW  = 136;             // W stride    (conflict-free B-frag)
static constexpr int LDA  = 28;              // A-tile stride (conflict-free A-frag)

// Shared layout (floats)
static constexpr int OFF_H   = 0;                          // [96][68]
static constexpr int OFF_ZH  = OFF_H  + MROW * LDH;        // [96][68]
static constexpr int OFF_ZL  = OFF_ZH + MROW * LDH;        // [96][68]
static constexpr int OFF_PQ  = OFF_ZL + MROW * LDH;        // [96][72]
static constexpr int OFF_PR  = OFF_PQ + MROW * LDP;        // [96][72]
static constexpr int OFF_W   = OFF_PR + MROW * LDP;        // [64][136] raw fp32 [Wr|Wo]
static constexpr int OFF_A   = OFF_W  + 64 * LDW;          // [4][32][28]
static constexpr int OFF_LNG = OFF_A  + G * 32 * LDA;
static constexpr int OFF_LNB = OFF_LNG + 64;
static constexpr int OFF_BRL = OFF_LNB + 64;
static constexpr int OFF_BEN = OFF_BRL + 64;
static constexpr int SM_FLOATS = OFF_BEN + 64;             // 45952
static constexpr int SM_BYTES  = SM_FLOATS * 4;            // 183808 B

// Device scratch (allocation-free rule: __device__ globals)
__device__ float g_A[(size_t)NUM_GRAPHS * A_STRIDE];
__device__ float g_pooled[(size_t)NUM_GRAPHS * HDIM];

// ---------------------------------------------------------------------------
__device__ __forceinline__ float tf32f(float x) {
    uint32_t y;
    asm("cvt.rna.tf32.f32 %0, %1;" : "=r"(y) : "f"(x));
    return __uint_as_float(y);
}

// D += A*B  (m16n8k8, tf32 inputs, fp32 accumulate)   [validated mapping, R8]
__device__ __forceinline__ void mma_tf32(float4& d,
                                         uint32_t a0, uint32_t a1,
                                         uint32_t a2, uint32_t a3,
                                         uint32_t b0, uint32_t b1) {
    asm volatile(
        "mma.sync.aligned.m16n8k8.row.col.f32.tf32.tf32.f32 "
        "{%0,%1,%2,%3}, {%4,%5,%6,%7}, {%8,%9}, {%0,%1,%2,%3};\n"
        : "+f"(d.x), "+f"(d.y), "+f"(d.z), "+f"(d.w)
        : "r"(a0), "r"(a1), "r"(a2), "r"(a3), "r"(b0), "r"(b1));
}

// A-fragment (16x8, row-major)   [validated mapping, R8]
__device__ __forceinline__ void ldA(const float* buf, int ld, int row0, int col0,
                                    int gr, int tg,
                                    uint32_t& a0, uint32_t& a1,
                                    uint32_t& a2, uint32_t& a3) {
    a0 = __float_as_uint(buf[(row0 + gr)     * ld + col0 + tg]);
    a1 = __float_as_uint(buf[(row0 + gr + 8) * ld + col0 + tg]);
    a2 = __float_as_uint(buf[(row0 + gr)     * ld + col0 + tg + 4]);
    a3 = __float_as_uint(buf[(row0 + gr + 8) * ld + col0 + tg + 4]);
}

// B-fragment (8x8) from fp32 buffer with ON-THE-FLY hi/lo tf32 split.
// buf holds full-precision fp32; residual v - tf32(v) is exact (Sterbenz).
__device__ __forceinline__ void ldB_split(const float* buf, int ld, int k0, int n0,
                                          int gr, int tg,
                                          uint32_t& bh0, uint32_t& bh1,
                                          uint32_t& bl0, uint32_t& bl1) {
    float v0 = buf[(k0 + tg)     * ld + n0 + gr];
    float v1 = buf[(k0 + tg + 4) * ld + n0 + gr];
    float h0 = tf32f(v0), h1 = tf32f(v1);
    bh0 = __float_as_uint(h0);
    bh1 = __float_as_uint(h1);
    bl0 = __float_as_uint(tf32f(v0 - h0));
    bl1 = __float_as_uint(tf32f(v1 - h1));
}

// ---------------------------------------------------------------------------
__global__ void zeroA_kernel() {
    const int n4 = NUM_GRAPHS * A_STRIDE / 4;
    float4* p = reinterpret_cast<float4*>(g_A);
    for (int i = blockIdx.x * blockDim.x + threadIdx.x; i < n4;
         i += gridDim.x * blockDim.x)
        p[i] = make_float4(0.f, 0.f, 0.f, 0.f);
}

__global__ void buildA_kernel(const int* __restrict__ ei) {
    int e = blockIdx.x * blockDim.x + threadIdx.x;
    if (e >= E_TOTAL) return;
    int s = ei[e];
    int d = ei[E_TOTAL + e];
    int g  = d / NG;
    int li = d - g * NG;
    int lj = s - g * NG;
    atomicAdd(&g_A[(size_t)g * A_STRIDE + li * NG + lj], 1.0f);
}

// ---------------------------------------------------------------------------
__global__ void __launch_bounds__(TPB, 1) gcn_main(
    const float* __restrict__ x,
    const float* __restrict__ W_enc, const float* __restrict__ b_enc,
    const float* __restrict__ ln_g,  const float* __restrict__ ln_b,
    const float* __restrict__ W_rel, const float* __restrict__ b_rel,
    const float* __restrict__ W_root)
{
    extern __shared__ float sm[];
    float* Hs  = sm + OFF_H;
    float* Zh  = sm + OFF_ZH;
    float* Zl  = sm + OFF_ZL;
    float* Pq  = sm + OFF_PQ;
    float* Pr  = sm + OFF_PR;
    float* Ws  = sm + OFF_W;
    float* As  = sm + OFF_A;
    float* lng = sm + OFF_LNG;
    float* lnb = sm + OFF_LNB;
    float* brl = sm + OFF_BRL;
    float* ben = sm + OFF_BEN;

    const int tid  = threadIdx.x;
    const int warp = tid >> 5;
    const int lane = tid & 31;
    const int gr   = lane >> 2;
    const int tg   = lane & 3;
    const int g0   = blockIdx.x * G;

    // ---- one-time staging: encoder W (raw, rows 0..7 of Ws), A tiles ------
    for (int i = tid; i < 8 * HDIM; i += TPB)
        Ws[(i >> 6) * LDW + (i & 63)] = W_enc[i];
    if (tid < HDIM) ben[tid] = b_enc[tid];
    for (int idx = tid; idx < G * 32 * LDA; idx += TPB) {
        int gl  = idx / (32 * LDA);
        int rem = idx - gl * (32 * LDA);
        int li  = rem / LDA;
        int lj  = rem - li * LDA;
        float v = 0.f;
        if (li < NG && lj < NG)
            v = g_A[(size_t)(g0 + gl) * A_STRIDE + li * NG + lj];
        As[idx] = v;     // small ints: exact in tf32 even as raw fp32 bits
    }
    __syncthreads();

    // ---- encoder: H = x @ W_enc + b_enc (fp32, one thread per row) --------
    if (tid < MROW) {
        int gl = tid / 24, node = tid - gl * 24;
        float* hr = Hs + tid * LDH;
        if (node < NG) {
            const float4* xr = reinterpret_cast<const float4*>(
                x + (size_t)((g0 + gl) * NG + node) * 8);
            float4 xa = xr[0], xb = xr[1];
            float xv[8] = {xa.x, xa.y, xa.z, xa.w, xb.x, xb.y, xb.z, xb.w};
            for (int n = 0; n < HDIM; n++) {
                float a = ben[n];
                #pragma unroll
                for (int k = 0; k < 8; k++) a = fmaf(xv[k], Ws[k * LDW + n], a);
                hr[n] = a;
            }
        } else {
            for (int n = 0; n < HDIM; n++) hr[n] = 0.f;   // pad row
        }
    }

    // ---- layer loop --------------------------------------------------------
    for (int l = 0; l < NLAYERS; l++) {
        __syncthreads();   // Hs final; prior reads of Ws/Z/P complete

        // phase 1: stage raw weights [Wr|Wo] + LN params
        {
            const float4* Wr4 = reinterpret_cast<const float4*>(W_rel  + l * 4096);
            const float4* Wo4 = reinterpret_cast<const float4*>(W_root + l * 4096);
            for (int i = tid; i < 1024; i += TPB) {
                int k  = i >> 4;          // 64 rows x 16 float4
                int n4 = (i & 15) * 4;
                *reinterpret_cast<float4*>(&Ws[k * LDW + n4])      = Wr4[i];
                *reinterpret_cast<float4*>(&Ws[k * LDW + 64 + n4]) = Wo4[i];
            }
            if (tid < HDIM) {
                lng[tid] = ln_g[l * HDIM + tid];
                lnb[tid] = ln_b[l * HDIM + tid];
                brl[tid] = b_rel[l * HDIM + tid];
            }
        }
        __syncthreads();

        // phase 2: Z = relu(LN(H)) split hi/lo (fp32 math, tid<96)
        if (tid < MROW) {
            const float* hr = Hs + tid * LDH;
            float v[HDIM];
            float mu = 0.f;
            #pragma unroll
            for (int i = 0; i < 16; i++) {
                float4 t = *reinterpret_cast<const float4*>(hr + 4 * i);
                v[4*i] = t.x; v[4*i+1] = t.y; v[4*i+2] = t.z; v[4*i+3] = t.w;
                mu += t.x + t.y + t.z + t.w;
            }
            mu *= (1.f / HDIM);
            float var = 0.f;
            #pragma unroll
            for (int i = 0; i < HDIM; i++) {
                float d = v[i] - mu;
                var = fmaf(d, d, var);
            }
            float rs = rsqrtf(var * (1.f / HDIM) + 1e-5f);
            float* zh = Zh + tid * LDH;
            float* zl = Zl + tid * LDH;
            #pragma unroll
            for (int i = 0; i < HDIM; i++) {
                float z  = fmaxf(fmaf((v[i] - mu) * rs, lng[i], lnb[i]), 0.f);
                float hi = tf32f(z);
                zh[i] = hi;
                zl[i] = tf32f(z - hi);
            }
        }
        __syncthreads();

        // phase 3: GEMM1  P = Z @ [Wr|Wo]  (M=96, K=64, N=128)
        // 8 warps, one (m48, n32) unit each: mhalf = warp>>2, nq = warp&3.
        {
            const int row0 = (warp >> 2) * 48;
            const int col0 = (warp & 3) * 32;
            float4 acc[3][4];
            #pragma unroll
            for (int mt = 0; mt < 3; mt++)
                #pragma unroll
                for (int nt = 0; nt < 4; nt++)
                    acc[mt][nt] = make_float4(0.f, 0.f, 0.f, 0.f);

            #pragma unroll
            for (int kt = 0; kt < 8; kt++) {
                uint32_t ah[3][4], al[3][4];
                #pragma unroll
                for (int mt = 0; mt < 3; mt++) {
                    ldA(Zh, LDH, row0 + mt * 16, kt * 8, gr, tg,
                        ah[mt][0], ah[mt][1], ah[mt][2], ah[mt][3]);
                    ldA(Zl, LDH, row0 + mt * 16, kt * 8, gr, tg,
                        al[mt][0], al[mt][1], al[mt][2], al[mt][3]);
                }
                #pragma unroll
                for (int nt = 0; nt < 4; nt++) {
                    uint32_t bh0, bh1, bl0, bl1;
                    ldB_split(Ws, LDW, kt * 8, col0 + nt * 8, gr, tg,
                              bh0, bh1, bl0, bl1);
                    #pragma unroll
                    for (int mt = 0; mt < 3; mt++) {
                        mma_tf32(acc[mt][nt], ah[mt][0], ah[mt][1], ah[mt][2], ah[mt][3], bh0, bh1);
                        mma_tf32(acc[mt][nt], ah[mt][0], ah[mt][1], ah[mt][2], ah[mt][3], bl0, bl1);
                        mma_tf32(acc[mt][nt], al[mt][0], al[mt][1], al[mt][2], al[mt][3], bh0, bh1);
                    }
                }
            }
            float* dst = (col0 < 64) ? Pq : Pr;
            const int cb = col0 & 63;
            #pragma unroll
            for (int mt = 0; mt < 3; mt++) {
                #pragma unroll
                for (int nt = 0; nt < 4; nt++) {
                    int r = row0 + mt * 16 + gr;
                    int c = cb + nt * 8 + 2 * tg;
                    *reinterpret_cast<float2*>(&dst[r * LDP + c]) =
                        make_float2(acc[mt][nt].x, acc[mt][nt].y);
                    *reinterpret_cast<float2*>(&dst[(r + 8) * LDP + c]) =
                        make_float2(acc[mt][nt].z, acc[mt][nt].w);
                }
            }
        }
        __syncthreads();

        // phase 4: GEMM2  H += A @ Pq + Pr + b_rel
        // 8 warps, one (m16, n64) job each: gj = warp>>1, mt = warp&1.
        {
            const int gj   = warp >> 1;
            const int mt   = warp & 1;
            const int rb   = gj * 24;
            const int row0 = rb + mt * 16;
            const float* Aw = As + gj * (32 * LDA);

            float4 acc[8];
            #pragma unroll
            for (int nt = 0; nt < 8; nt++) {
                int c = nt * 8 + 2 * tg;
                int ra = row0 + gr;
                acc[nt].x = Hs[ra * LDH + c]     + Pr[ra * LDP + c]     + brl[c];
                acc[nt].y = Hs[ra * LDH + c + 1] + Pr[ra * LDP + c + 1] + brl[c + 1];
                if (mt == 0) {
                    int rz = ra + 8;
                    acc[nt].z = Hs[rz * LDH + c]     + Pr[rz * LDP + c]     + brl[c];
                    acc[nt].w = Hs[rz * LDH + c + 1] + Pr[rz * LDP + c + 1] + brl[c + 1];
                } else {
                    acc[nt].z = 0.f;   // rows 24..31 = pad/next graph: not stored
                    acc[nt].w = 0.f;
                }
            }
            #pragma unroll
            for (int kt = 0; kt < 3; kt++) {
                uint32_t a0, a1, a2, a3;     // raw fp32 ints == exact tf32
                ldA(Aw, LDA, mt * 16, kt * 8, gr, tg, a0, a1, a2, a3);
                #pragma unroll
                for (int nt = 0; nt < 8; nt++) {
                    uint32_t bh0, bh1, bl0, bl1;
                    ldB_split(Pq, LDP, rb + kt * 8, nt * 8, gr, tg,
                              bh0, bh1, bl0, bl1);
                    mma_tf32(acc[nt], a0, a1, a2, a3, bh0, bh1);
                    mma_tf32(acc[nt], a0, a1, a2, a3, bl0, bl1);
                }
            }
            #pragma unroll
            for (int nt = 0; nt < 8; nt++) {
                int c = nt * 8 + 2 * tg;
                int ra = row0 + gr;
                *reinterpret_cast<float2*>(&Hs[ra * LDH + c]) =
                    make_float2(acc[nt].x, acc[nt].y);
                if (mt == 0) {
                    *reinterpret_cast<float2*>(&Hs[(ra + 8) * LDH + c]) =
                        make_float2(acc[nt].z, acc[nt].w);
                }
            }
        }
    }

    // ---- per-graph mean pool (exclude pad rows) ----------------------------
    __syncthreads();
    {
        int gl = tid >> 6;
        int f  = tid & 63;
        const float* hb = Hs + (gl * 24) * LDH + f;
        float s = 0.f;
        #pragma unroll
        for (int i = 0; i < NG; i++) s += hb[i * LDH];
        g_pooled[(size_t)(g0 + gl) * HDIM + f] = s * (1.f / NG);
    }
}

// ---------------------------------------------------------------------------
__global__ void head_kernel(const float* __restrict__ pos,
                            const float* __restrict__ W1, const float* __restrict__ b1,
                            const float* __restrict__ W2, const float* __restrict__ b2,
                            float* __restrict__ out)
{
    __shared__ float vs[HDIM];
    __shared__ float h1s[HDIM];
    const int b = blockIdx.x;
    const int f = threadIdx.x;

    float v = 0.f;
    #pragma unroll
    for (int tt = 0; tt < NT; tt++)
        v += g_pooled[(size_t)(b * NT + tt) * HDIM + f] + pos[tt * HDIM + f];
    vs[f] = v * (1.f / NT);
    __syncthreads();

    float acc = b1[f];
    #pragma unroll
    for (int k = 0; k < HDIM; k++) acc = fmaf(vs[k], W1[k * HDIM + f], acc);
    h1s[f] = fmaxf(acc, 0.f);
    __syncthreads();

    if (f < NC) {
        float o = b2[f];
        #pragma unroll
        for (int k = 0; k < HDIM; k++) o = fmaf(h1s[k], W2[k * NC + f], o);
        out[b * NC + f] = o;
    }
}

// ---------------------------------------------------------------------------
extern "C" void kernel_launch(void* const* d_in, const int* in_sizes, int n_in,
                              void* d_out, int out_size)
{
    const float* x     = (const float*)d_in[0];
    const int*   ei    = (const int*)  d_in[1];
    // d_in[2] = batch (unused: graphs are contiguous blocks of 23 nodes)
    const float* W_enc = (const float*)d_in[3];
    const float* b_enc = (const float*)d_in[4];
    const float* ln_g  = (const float*)d_in[5];
    const float* ln_b  = (const float*)d_in[6];
    const float* W_rel = (const float*)d_in[7];
    const float* b_rel = (const float*)d_in[8];
    const float* W_root= (const float*)d_in[9];
    const float* pos   = (const float*)d_in[10];
    const float* W1    = (const float*)d_in[11];
    const float* b1    = (const float*)d_in[12];
    const float* W2    = (const float*)d_in[13];
    const float* b2    = (const float*)d_in[14];
    float* out = (float*)d_out;

    (void)in_sizes; (void)n_in; (void)out_size;

    cudaFuncSetAttribute(gcn_main, cudaFuncAttributeMaxDynamicSharedMemorySize,
                         SM_BYTES);

    zeroA_kernel<<<1024, 256>>>();
    buildA_kernel<<<(E_TOTAL + 255) / 256, 256>>>(ei);
    gcn_main<<<NUM_GRAPHS / G, TPB, SM_BYTES>>>(
        x, W_enc, b_enc, ln_g, ln_b, W_rel, b_rel, W_root);
    head_kernel<<<NB, HDIM>>>(pos, W1, b1, W2, b2, out);
}

// round 15
// speedup vs baseline: 1.5659x; 1.0908x over previous
#include <cuda_runtime.h>
#include <cstdint>

// ---------------------------------------------------------------------------
// DeepGCN fused kernel, round 14 = R10 verbatim (validated: 3740us, 2.8e-6)
// + ONE minimal value-preserving diff: cp.async double-buffered weight
// prefetch (layer l+1 weights fetched during layer l's compute).
//
//   Z = relu(LN(H));  P = Z @ [Wr | Wo]  (3 mma products: hh + hl + lh);
//   H += A @ P[:, :64] + P[:, 64:] + b_rel   (A exact in tf32, 2 products).
// ---------------------------------------------------------------------------

static constexpr int NUM_GRAPHS = 16384;
static constexpr int NG        = 23;
static constexpr int E_TOTAL   = 4194304;
static constexpr int HDIM      = 64;
static constexpr int NLAYERS   = 20;
static constexpr int NB        = 1024;
static constexpr int NT        = 16;
static constexpr int NC        = 3;
static constexpr int A_STRIDE  = NG * NG;    // 529

static constexpr int G    = 4;               // graphs per block
static constexpr int TPB  = 256;             // 8 warps
static constexpr int MROW = G * 24;          // 96 rows
static constexpr int LDH  = 68;              // H/Z stride  (conflict-free A-frag)
static constexpr int LDP  = 72;              // P stride    (conflict-free B-frag)
static constexpr int LDW  = 136;             // W stride    (conflict-free B-frag)
static constexpr int LDA  = 28;              // A-tile stride

// Shared layout (floats) — R10 layout with W double-buffered
static constexpr int OFF_H   = 0;                          // [96][68]
static constexpr int OFF_ZH  = OFF_H  + MROW * LDH;        // [96][68]
static constexpr int OFF_ZL  = OFF_ZH + MROW * LDH;        // [96][68]
static constexpr int OFF_PQ  = OFF_ZL + MROW * LDH;        // [96][72]
static constexpr int OFF_PR  = OFF_PQ + MROW * LDP;        // [96][72]
static constexpr int OFF_W0  = OFF_PR + MROW * LDP;        // [64][136] raw fp32 buf0
static constexpr int OFF_W1  = OFF_W0 + 64 * LDW;          // [64][136] raw fp32 buf1
static constexpr int OFF_A   = OFF_W1 + 64 * LDW;          // [4][32][28]
static constexpr int OFF_LNG = OFF_A  + G * 32 * LDA;
static constexpr int OFF_LNB = OFF_LNG + 64;
static constexpr int OFF_BRL = OFF_LNB + 64;
static constexpr int OFF_BEN = OFF_BRL + 64;
static constexpr int SM_FLOATS = OFF_BEN + 64;             // 54656
static constexpr int SM_BYTES  = SM_FLOATS * 4;            // 218624 B (< 227KB)

// Device scratch (allocation-free rule: __device__ globals)
__device__ float g_A[(size_t)NUM_GRAPHS * A_STRIDE];
__device__ float g_pooled[(size_t)NUM_GRAPHS * HDIM];

// ---------------------------------------------------------------------------
__device__ __forceinline__ float tf32f(float x) {
    uint32_t y;
    asm("cvt.rna.tf32.f32 %0, %1;" : "=r"(y) : "f"(x));
    return __uint_as_float(y);
}

// D += A*B  (m16n8k8, tf32 inputs, fp32 accumulate)   [validated R8/R10]
__device__ __forceinline__ void mma_tf32(float4& d,
                                         uint32_t a0, uint32_t a1,
                                         uint32_t a2, uint32_t a3,
                                         uint32_t b0, uint32_t b1) {
    asm volatile(
        "mma.sync.aligned.m16n8k8.row.col.f32.tf32.tf32.f32 "
        "{%0,%1,%2,%3}, {%4,%5,%6,%7}, {%8,%9}, {%0,%1,%2,%3};\n"
        : "+f"(d.x), "+f"(d.y), "+f"(d.z), "+f"(d.w)
        : "r"(a0), "r"(a1), "r"(a2), "r"(a3), "r"(b0), "r"(b1));
}

// A-fragment (16x8, row-major)   [validated mapping, R8/R10]
__device__ __forceinline__ void ldA(const float* buf, int ld, int row0, int col0,
                                    int gr, int tg,
                                    uint32_t& a0, uint32_t& a1,
                                    uint32_t& a2, uint32_t& a3) {
    a0 = __float_as_uint(buf[(row0 + gr)     * ld + col0 + tg]);
    a1 = __float_as_uint(buf[(row0 + gr + 8) * ld + col0 + tg]);
    a2 = __float_as_uint(buf[(row0 + gr)     * ld + col0 + tg + 4]);
    a3 = __float_as_uint(buf[(row0 + gr + 8) * ld + col0 + tg + 4]);
}

// B-fragment (8x8) from fp32 buffer with ON-THE-FLY hi/lo tf32 split.
__device__ __forceinline__ void ldB_split(const float* buf, int ld, int k0, int n0,
                                          int gr, int tg,
                                          uint32_t& bh0, uint32_t& bh1,
                                          uint32_t& bl0, uint32_t& bl1) {
    float v0 = buf[(k0 + tg)     * ld + n0 + gr];
    float v1 = buf[(k0 + tg + 4) * ld + n0 + gr];
    float h0 = tf32f(v0), h1 = tf32f(v1);
    bh0 = __float_as_uint(h0);
    bh1 = __float_as_uint(h1);
    bl0 = __float_as_uint(tf32f(v0 - h0));
    bl1 = __float_as_uint(tf32f(v1 - h1));
}

// cp.async helpers (mechanism only; same bytes to same logical slots)
__device__ __forceinline__ void cp_async16(void* smem_dst, const void* gsrc) {
    uint32_t s = (uint32_t)__cvta_generic_to_shared(smem_dst);
    asm volatile("cp.async.cg.shared.global [%0], [%1], 16;\n"
                 :: "r"(s), "l"(gsrc) : "memory");
}
__device__ __forceinline__ void cp_commit() {
    asm volatile("cp.async.commit_group;\n" ::: "memory");
}
__device__ __forceinline__ void cp_wait1() {
    asm volatile("cp.async.wait_group 1;\n" ::: "memory");
}
__device__ __forceinline__ void cp_wait0() {
    asm volatile("cp.async.wait_group 0;\n" ::: "memory");
}

// ---------------------------------------------------------------------------
__global__ void zeroA_kernel() {
    const int n4 = NUM_GRAPHS * A_STRIDE / 4;
    float4* p = reinterpret_cast<float4*>(g_A);
    for (int i = blockIdx.x * blockDim.x + threadIdx.x; i < n4;
         i += gridDim.x * blockDim.x)
        p[i] = make_float4(0.f, 0.f, 0.f, 0.f);
}

__global__ void buildA_kernel(const int* __restrict__ ei) {
    int e = blockIdx.x * blockDim.x + threadIdx.x;
    if (e >= E_TOTAL) return;
    int s = ei[e];
    int d = ei[E_TOTAL + e];
    int g  = d / NG;
    int li = d - g * NG;
    int lj = s - g * NG;
    atomicAdd(&g_A[(size_t)g * A_STRIDE + li * NG + lj], 1.0f);
}

// ---------------------------------------------------------------------------
__global__ void __launch_bounds__(TPB, 1) gcn_main(
    const float* __restrict__ x,
    const float* __restrict__ W_enc, const float* __restrict__ b_enc,
    const float* __restrict__ ln_g,  const float* __restrict__ ln_b,
    const float* __restrict__ W_rel, const float* __restrict__ b_rel,
    const float* __restrict__ W_root)
{
    extern __shared__ float sm[];
    float* Hs  = sm + OFF_H;
    float* Zh  = sm + OFF_ZH;
    float* Zl  = sm + OFF_ZL;
    float* Pq  = sm + OFF_PQ;
    float* Pr  = sm + OFF_PR;
    float* As  = sm + OFF_A;
    float* lng = sm + OFF_LNG;
    float* lnb = sm + OFF_LNB;
    float* brl = sm + OFF_BRL;
    float* ben = sm + OFF_BEN;
    float* Wenc_s = sm + OFF_W1;   // encoder weights parked in buf1 (layer 0
                                   // uses buf0; buf1 first overwritten at the
                                   // top of layer 0, after encoder reads)

    const int tid  = threadIdx.x;
    const int warp = tid >> 5;
    const int lane = tid & 31;
    const int gr   = lane >> 2;
    const int tg   = lane & 3;
    const int g0   = blockIdx.x * G;

    // ---- one-time staging: encoder W raw, A tiles; prefetch layer0 W ------
    for (int i = tid; i < 8 * HDIM; i += TPB)
        Wenc_s[(i >> 6) * LDW + (i & 63)] = W_enc[i];
    if (tid < HDIM) ben[tid] = b_enc[tid];
    for (int idx = tid; idx < G * 32 * LDA; idx += TPB) {
        int gl  = idx / (32 * LDA);
        int rem = idx - gl * (32 * LDA);
        int li  = rem / LDA;
        int lj  = rem - li * LDA;
        float v = 0.f;
        if (li < NG && lj < NG)
            v = g_A[(size_t)(g0 + gl) * A_STRIDE + li * NG + lj];
        As[idx] = v;     // small ints: exact in tf32 even as raw fp32 bits
    }
    {   // prefetch layer 0 weights into buf0
        const float4* Wr4 = reinterpret_cast<const float4*>(W_rel);
        const float4* Wo4 = reinterpret_cast<const float4*>(W_root);
        float* Wd = sm + OFF_W0;
        for (int i = tid; i < 1024; i += TPB) {
            int k  = i >> 4;
            int n4 = (i & 15) * 4;
            cp_async16(&Wd[k * LDW + n4],      Wr4 + i);
            cp_async16(&Wd[k * LDW + 64 + n4], Wo4 + i);
        }
        cp_commit();
    }
    __syncthreads();

    // ---- encoder: H = x @ W_enc + b_enc (fp32, one thread per row) --------
    if (tid < MROW) {
        int gl = tid / 24, node = tid - gl * 24;
        float* hr = Hs + tid * LDH;
        if (node < NG) {
            const float4* xr = reinterpret_cast<const float4*>(
                x + (size_t)((g0 + gl) * NG + node) * 8);
            float4 xa = xr[0], xb = xr[1];
            float xv[8] = {xa.x, xa.y, xa.z, xa.w, xb.x, xb.y, xb.z, xb.w};
            for (int n = 0; n < HDIM; n++) {
                float a = ben[n];
                #pragma unroll
                for (int k = 0; k < 8; k++) a = fmaf(xv[k], Wenc_s[k * LDW + n], a);
                hr[n] = a;
            }
        } else {
            for (int n = 0; n < HDIM; n++) hr[n] = 0.f;   // pad row
        }
    }

    // ---- layer loop --------------------------------------------------------
    for (int l = 0; l < NLAYERS; l++) {
        __syncthreads();   // Hs final; prior reads of Ws/Z/P complete

        // phase 1: issue cp.async prefetch of layer l+1 weights (alt buffer)
        //          + stage LN params (verbatim R10 values)
        {
            if (l + 1 < NLAYERS) {
                const int lp = l + 1;
                const float4* Wr4 = reinterpret_cast<const float4*>(W_rel  + lp * 4096);
                const float4* Wo4 = reinterpret_cast<const float4*>(W_root + lp * 4096);
                float* Wd = sm + ((lp & 1) ? OFF_W1 : OFF_W0);
                for (int i = tid; i < 1024; i += TPB) {
                    int k  = i >> 4;
                    int n4 = (i & 15) * 4;
                    cp_async16(&Wd[k * LDW + n4],      Wr4 + i);
                    cp_async16(&Wd[k * LDW + 64 + n4], Wo4 + i);
                }
                cp_commit();
            }
            if (tid < HDIM) {
                lng[tid] = ln_g[l * HDIM + tid];
                lnb[tid] = ln_b[l * HDIM + tid];
                brl[tid] = b_rel[l * HDIM + tid];
            }
        }
        __syncthreads();

        // phase 2: Z = relu(LN(H)) split hi/lo (fp32 math, tid<96) [verbatim]
        if (tid < MROW) {
            const float* hr = Hs + tid * LDH;
            float v[HDIM];
            float mu = 0.f;
            #pragma unroll
            for (int i = 0; i < 16; i++) {
                float4 t = *reinterpret_cast<const float4*>(hr + 4 * i);
                v[4*i] = t.x; v[4*i+1] = t.y; v[4*i+2] = t.z; v[4*i+3] = t.w;
                mu += t.x + t.y + t.z + t.w;
            }
            mu *= (1.f / HDIM);
            float var = 0.f;
            #pragma unroll
            for (int i = 0; i < HDIM; i++) {
                float d = v[i] - mu;
                var = fmaf(d, d, var);
            }
            float rs = rsqrtf(var * (1.f / HDIM) + 1e-5f);
            float* zh = Zh + tid * LDH;
            float* zl = Zl + tid * LDH;
            #pragma unroll
            for (int i = 0; i < HDIM; i++) {
                float z  = fmaxf(fmaf((v[i] - mu) * rs, lng[i], lnb[i]), 0.f);
                float hi = tf32f(z);
                zh[i] = hi;
                zl[i] = tf32f(z - hi);
            }
        }
        // layer l's weights must be resident before GEMM1 reads them
        if (l + 1 < NLAYERS) cp_wait1(); else cp_wait0();
        __syncthreads();   // Z + W(buf l&1) ready

        const float* Ws = sm + ((l & 1) ? OFF_W1 : OFF_W0);

        // phase 3: GEMM1  P = Z @ [Wr|Wo]  (M=96, K=64, N=128)  [verbatim R10]
        // 8 warps, one (m48, n32) unit each: mhalf = warp>>2, nq = warp&3.
        {
            const int row0 = (warp >> 2) * 48;
            const int col0 = (warp & 3) * 32;
            float4 acc[3][4];
            #pragma unroll
            for (int mt = 0; mt < 3; mt++)
                #pragma unroll
                for (int nt = 0; nt < 4; nt++)
                    acc[mt][nt] = make_float4(0.f, 0.f, 0.f, 0.f);

            #pragma unroll
            for (int kt = 0; kt < 8; kt++) {
                uint32_t ah[3][4], al[3][4];
                #pragma unroll
                for (int mt = 0; mt < 3; mt++) {
                    ldA(Zh, LDH, row0 + mt * 16, kt * 8, gr, tg,
                        ah[mt][0], ah[mt][1], ah[mt][2], ah[mt][3]);
                    ldA(Zl, LDH, row0 + mt * 16, kt * 8, gr, tg,
                        al[mt][0], al[mt][1], al[mt][2], al[mt][3]);
                }
                #pragma unroll
                for (int nt = 0; nt < 4; nt++) {
                    uint32_t bh0, bh1, bl0, bl1;
                    ldB_split(Ws, LDW, kt * 8, col0 + nt * 8, gr, tg,
                              bh0, bh1, bl0, bl1);
                    #pragma unroll
                    for (int mt = 0; mt < 3; mt++) {
                        mma_tf32(acc[mt][nt], ah[mt][0], ah[mt][1], ah[mt][2], ah[mt][3], bh0, bh1);
                        mma_tf32(acc[mt][nt], ah[mt][0], ah[mt][1], ah[mt][2], ah[mt][3], bl0, bl1);
                        mma_tf32(acc[mt][nt], al[mt][0], al[mt][1], al[mt][2], al[mt][3], bh0, bh1);
                    }
                }
            }
            float* dst = (col0 < 64) ? Pq : Pr;
            const int cb = col0 & 63;
            #pragma unroll
            for (int mt = 0; mt < 3; mt++) {
                #pragma unroll
                for (int nt = 0; nt < 4; nt++) {
                    int r = row0 + mt * 16 + gr;
                    int c = cb + nt * 8 + 2 * tg;
                    *reinterpret_cast<float2*>(&dst[r * LDP + c]) =
                        make_float2(acc[mt][nt].x, acc[mt][nt].y);
                    *reinterpret_cast<float2*>(&dst[(r + 8) * LDP + c]) =
                        make_float2(acc[mt][nt].z, acc[mt][nt].w);
                }
            }
        }
        __syncthreads();   // Ps ready

        // phase 4: GEMM2  H += A @ Pq + Pr + b_rel   [verbatim R10]
        // 8 warps, one (m16, n64) job each: gj = warp>>1, mt = warp&1.
        {
            const int gj   = warp >> 1;
            const int mt   = warp & 1;
            const int rb   = gj * 24;
            const int row0 = rb + mt * 16;
            const float* Aw = As + gj * (32 * LDA);

            float4 acc[8];
            #pragma unroll
            for (int nt = 0; nt < 8; nt++) {
                int c = nt * 8 + 2 * tg;
                int ra = row0 + gr;
                acc[nt].x = Hs[ra * LDH + c]     + Pr[ra * LDP + c]     + brl[c];
                acc[nt].y = Hs[ra * LDH + c + 1] + Pr[ra * LDP + c + 1] + brl[c + 1];
                if (mt == 0) {
                    int rz = ra + 8;
                    acc[nt].z = Hs[rz * LDH + c]     + Pr[rz * LDP + c]     + brl[c];
                    acc[nt].w = Hs[rz * LDH + c + 1] + Pr[rz * LDP + c + 1] + brl[c + 1];
                } else {
                    acc[nt].z = 0.f;   // rows 24..31 = pad/next graph: not stored
                    acc[nt].w = 0.f;
                }
            }
            #pragma unroll
            for (int kt = 0; kt < 3; kt++) {
                uint32_t a0, a1, a2, a3;     // raw fp32 ints == exact tf32
                ldA(Aw, LDA, mt * 16, kt * 8, gr, tg, a0, a1, a2, a3);
                #pragma unroll
                for (int nt = 0; nt < 8; nt++) {
                    uint32_t bh0, bh1, bl0, bl1;
                    ldB_split(Pq, LDP, rb + kt * 8, nt * 8, gr, tg,
                              bh0, bh1, bl0, bl1);
                    mma_tf32(acc[nt], a0, a1, a2, a3, bh0, bh1);
                    mma_tf32(acc[nt], a0, a1, a2, a3, bl0, bl1);
                }
            }
            #pragma unroll
            for (int nt = 0; nt < 8; nt++) {
                int c = nt * 8 + 2 * tg;
                int ra = row0 + gr;
                *reinterpret_cast<float2*>(&Hs[ra * LDH + c]) =
                    make_float2(acc[nt].x, acc[nt].y);
                if (mt == 0) {
                    *reinterpret_cast<float2*>(&Hs[(ra + 8) * LDH + c]) =
                        make_float2(acc[nt].z, acc[nt].w);
                }
            }
        }
    }

    // ---- per-graph mean pool (exclude pad rows) ----------------------------
    __syncthreads();
    {
        int gl = tid >> 6;
        int f  = tid & 63;
        const float* hb = Hs + (gl * 24) * LDH + f;
        float s = 0.f;
        #pragma unroll
        for (int i = 0; i < NG; i++) s += hb[i * LDH];
        g_pooled[(size_t)(g0 + gl) * HDIM + f] = s * (1.f / NG);
    }
}

// ---------------------------------------------------------------------------
__global__ void head_kernel(const float* __restrict__ pos,
                            const float* __restrict__ W1, const float* __restrict__ b1,
                            const float* __restrict__ W2, const float* __restrict__ b2,
                            float* __restrict__ out)
{
    __shared__ float vs[HDIM];
    __shared__ float h1s[HDIM];
    const int b = blockIdx.x;
    const int f = threadIdx.x;

    float v = 0.f;
    #pragma unroll
    for (int tt = 0; tt < NT; tt++)
        v += g_pooled[(size_t)(b * NT + tt) * HDIM + f] + pos[tt * HDIM + f];
    vs[f] = v * (1.f / NT);
    __syncthreads();

    float acc = b1[f];
    #pragma unroll
    for (int k = 0; k < HDIM; k++) acc = fmaf(vs[k], W1[k * HDIM + f], acc);
    h1s[f] = fmaxf(acc, 0.f);
    __syncthreads();

    if (f < NC) {
        float o = b2[f];
        #pragma unroll
        for (int k = 0; k < HDIM; k++) o = fmaf(h1s[k], W2[k * NC + f], o);
        out[b * NC + f] = o;
    }
}

// ---------------------------------------------------------------------------
extern "C" void kernel_launch(void* const* d_in, const int* in_sizes, int n_in,
                              void* d_out, int out_size)
{
    const float* x     = (const float*)d_in[0];
    const int*   ei    = (const int*)  d_in[1];
    // d_in[2] = batch (unused: graphs are contiguous blocks of 23 nodes)
    const float* W_enc = (const float*)d_in[3];
    const float* b_enc = (const float*)d_in[4];
    const float* ln_g  = (const float*)d_in[5];
    const float* ln_b  = (const float*)d_in[6];
    const float* W_rel = (const float*)d_in[7];
    const float* b_rel = (const float*)d_in[8];
    const float* W_root= (const float*)d_in[9];
    const float* pos   = (const float*)d_in[10];
    const float* W1    = (const float*)d_in[11];
    const float* b1    = (const float*)d_in[12];
    const float* W2    = (const float*)d_in[13];
    const float* b2    = (const float*)d_in[14];
    float* out = (float*)d_out;

    (void)in_sizes; (void)n_in; (void)out_size;

    cudaFuncSetAttribute(gcn_main, cudaFuncAttributeMaxDynamicSharedMemorySize,
                         SM_BYTES);

    zeroA_kernel<<<1024, 256>>>();
    buildA_kernel<<<(E_TOTAL + 255) / 256, 256>>>(ei);
    gcn_main<<<NUM_GRAPHS / G, TPB, SM_BYTES>>>(
        x, W_enc, b_enc, ln_g, ln_b, W_rel, b_rel, W_root);
    head_kernel<<<NB, HDIM>>>(pos, W1, b1, W2, b2, out);
}